// round 1
// baseline (speedup 1.0000x reference)
#include <cuda_runtime.h>
#include <cuda_bf16.h>
#include <math.h>

// Problem constants (match reference)
#define BATCH       32
#define HEADS       16
#define HEADDIM     128
#define BLOCK_SIZE  16
#define MAX_BLOCKS  128
#define MAX_CTX     (MAX_BLOCKS * BLOCK_SIZE)   // 2048
#define SCALE       (0.08838834764831845f)      // 1/sqrt(128)

#define NWARPS      16
#define NTHREADS    (NWARPS * 32)

__global__ __launch_bounds__(NTHREADS, 2)
void paged_attn_kernel(const float* __restrict__ query,
                       const float* __restrict__ key_cache,
                       const float* __restrict__ value_cache,
                       const int*   __restrict__ block_tables,
                       const int*   __restrict__ context_lens,
                       float*       __restrict__ out)
{
    const int h    = blockIdx.x;
    const int b    = blockIdx.y;
    const int tid  = threadIdx.x;
    const int lane = tid & 31;
    const int warp = tid >> 5;

    __shared__ float s_scores[MAX_CTX];          // 8 KB
    __shared__ float s_acc[NWARPS * HEADDIM];    // 8 KB
    __shared__ int   s_btab[MAX_BLOCKS];         // 0.5 KB
    __shared__ float s_red[NWARPS];
    __shared__ float s_gmax, s_ginv;

    const int ctx = context_lens[b];

    if (tid < MAX_BLOCKS)
        s_btab[tid] = block_tables[b * MAX_BLOCKS + tid];
    __syncthreads();

    // Query slice for this (b,h): 128 floats -> one float4 per lane.
    const float4 q4 =
        reinterpret_cast<const float4*>(query + ((size_t)b * HEADS + h) * HEADDIM)[lane];

    // ---------------- Pass 1: scores = (q . k) * scale, track max -------------
    float lmax = -INFINITY;
    {
        int t = warp;
        float4 kcur;
        if (t < ctx) {
            const int blk = s_btab[t >> 4];
            kcur = reinterpret_cast<const float4*>(
                key_cache + (((size_t)blk * BLOCK_SIZE + (t & 15)) * HEADS + h) * HEADDIM)[lane];
        }
        for (; t < ctx; t += NWARPS) {
            const int tn = t + NWARPS;
            float4 knext;
            if (tn < ctx) {
                const int blk = s_btab[tn >> 4];
                knext = reinterpret_cast<const float4*>(
                    key_cache + (((size_t)blk * BLOCK_SIZE + (tn & 15)) * HEADS + h) * HEADDIM)[lane];
            }
            float d = kcur.x * q4.x + kcur.y * q4.y + kcur.z * q4.z + kcur.w * q4.w;
            #pragma unroll
            for (int o = 16; o; o >>= 1)
                d += __shfl_xor_sync(0xFFFFFFFFu, d, o);
            d *= SCALE;
            if (lane == 0) s_scores[t] = d;
            lmax = fmaxf(lmax, d);      // d identical across lanes after xor-reduce
            kcur = knext;
        }
    }

    // Block-wide max
    if (lane == 0) s_red[warp] = lmax;
    __syncthreads();
    if (tid == 0) {
        float m = -INFINITY;
        #pragma unroll
        for (int w = 0; w < NWARPS; w++) m = fmaxf(m, s_red[w]);
        s_gmax = m;
    }
    __syncthreads();
    const float gmax = s_gmax;

    // ---------------- Softmax: exp + sum ----------------
    float lsum = 0.0f;
    for (int i = tid; i < ctx; i += NTHREADS) {
        const float e = __expf(s_scores[i] - gmax);
        s_scores[i] = e;
        lsum += e;
    }
    #pragma unroll
    for (int o = 16; o; o >>= 1)
        lsum += __shfl_xor_sync(0xFFFFFFFFu, lsum, o);
    if (lane == 0) s_red[warp] = lsum;
    __syncthreads();
    if (tid == 0) {
        float s = 0.0f;
        #pragma unroll
        for (int w = 0; w < NWARPS; w++) s += s_red[w];
        s_ginv = 1.0f / s;
    }
    __syncthreads();

    // ---------------- Pass 2: out = sum_t p[t] * v[t] ----------------
    float4 acc = make_float4(0.f, 0.f, 0.f, 0.f);
    {
        int t = warp;
        float4 vcur;
        if (t < ctx) {
            const int blk = s_btab[t >> 4];
            vcur = reinterpret_cast<const float4*>(
                value_cache + (((size_t)blk * BLOCK_SIZE + (t & 15)) * HEADS + h) * HEADDIM)[lane];
        }
        for (; t < ctx; t += NWARPS) {
            const int tn = t + NWARPS;
            float4 vnext;
            if (tn < ctx) {
                const int blk = s_btab[tn >> 4];
                vnext = reinterpret_cast<const float4*>(
                    value_cache + (((size_t)blk * BLOCK_SIZE + (tn & 15)) * HEADS + h) * HEADDIM)[lane];
            }
            const float p = s_scores[t];
            acc.x += p * vcur.x;
            acc.y += p * vcur.y;
            acc.z += p * vcur.z;
            acc.w += p * vcur.w;
            vcur = vnext;
        }
    }

    // Combine warp partials
    reinterpret_cast<float4*>(&s_acc[warp * HEADDIM])[lane] = acc;
    __syncthreads();

    if (tid < HEADDIM) {
        float o = 0.0f;
        #pragma unroll
        for (int w = 0; w < NWARPS; w++) o += s_acc[w * HEADDIM + tid];
        out[((size_t)b * HEADS + h) * HEADDIM + tid] = o * s_ginv;
    }
}

extern "C" void kernel_launch(void* const* d_in, const int* in_sizes, int n_in,
                              void* d_out, int out_size)
{
    const float* query        = (const float*)d_in[0];
    const float* key_cache    = (const float*)d_in[1];
    const float* value_cache  = (const float*)d_in[2];
    const int*   block_tables = (const int*)d_in[3];
    const int*   context_lens = (const int*)d_in[4];
    float*       out          = (float*)d_out;

    dim3 grid(HEADS, BATCH);
    paged_attn_kernel<<<grid, NTHREADS>>>(query, key_cache, value_cache,
                                          block_tables, context_lens, out);
}

// round 3
// speedup vs baseline: 1.4430x; 1.4430x over previous
#include <cuda_runtime.h>
#include <cuda_bf16.h>
#include <math.h>

#define BATCH       32
#define HEADS       16
#define HEADDIM     128
#define BLOCK_SIZE  16
#define MAX_BLOCKS  128
#define MAX_CTX     (MAX_BLOCKS * BLOCK_SIZE)   // 2048
#define SCALE       (0.08838834764831845f)      // 1/sqrt(128)

#define NSPLIT      8
#define CHUNK       (MAX_CTX / NSPLIT)          // 256 tokens per split
#define NWARPS      8
#define NTHREADS    (NWARPS * 32)               // 256

// Split-KV partial results: per (b, h, split)
__device__ float g_m[BATCH * HEADS * NSPLIT];
__device__ float g_s[BATCH * HEADS * NSPLIT];
__device__ float g_acc[BATCH * HEADS * NSPLIT * HEADDIM];

__global__ __launch_bounds__(NTHREADS, 6)
void paged_attn_split_kernel(const float* __restrict__ query,
                             const float* __restrict__ key_cache,
                             const float* __restrict__ value_cache,
                             const int*   __restrict__ block_tables,
                             const int*   __restrict__ context_lens)
{
    const int h     = blockIdx.x;
    const int b     = blockIdx.y;
    const int split = blockIdx.z;
    const int tid   = threadIdx.x;
    const int lane  = tid & 31;
    const int warp  = tid >> 5;

    const int ctx   = context_lens[b];
    const int start = split * CHUNK;
    const int p     = (b * HEADS + h) * NSPLIT + split;

    if (start >= ctx) {
        // Inactive split: write neutral partial so reduce ignores it.
        if (tid == 0) { g_m[p] = -INFINITY; g_s[p] = 0.0f; }
        return;
    }
    const int end = min(start + CHUNK, ctx);

    __shared__ int   s_btab[CHUNK / BLOCK_SIZE];      // 16 entries
    __shared__ float s_wm[NWARPS], s_ws[NWARPS];
    __shared__ float s_acc[NWARPS * HEADDIM];         // 4 KB

    if (tid < CHUNK / BLOCK_SIZE)
        s_btab[tid] = block_tables[b * MAX_BLOCKS + (start >> 4) + tid];
    __syncthreads();

    const float4 q4 =
        reinterpret_cast<const float4*>(query + ((size_t)b * HEADS + h) * HEADDIM)[lane];

    // ---- Fused pass: online softmax over this chunk, one token per warp/iter ----
    float m = -INFINITY, s = 0.0f;
    float4 acc = make_float4(0.f, 0.f, 0.f, 0.f);

    int t = start + warp;
    float4 kc, vc;
    if (t < end) {
        const int blk  = s_btab[(t - start) >> 4];
        const size_t o = (((size_t)blk * BLOCK_SIZE + (t & 15)) * HEADS + h) * HEADDIM;
        kc = reinterpret_cast<const float4*>(key_cache   + o)[lane];
        vc = reinterpret_cast<const float4*>(value_cache + o)[lane];
    }
    for (; t < end; t += NWARPS) {
        const int tn = t + NWARPS;
        float4 kn, vn;
        if (tn < end) {
            const int blk  = s_btab[(tn - start) >> 4];
            const size_t o = (((size_t)blk * BLOCK_SIZE + (tn & 15)) * HEADS + h) * HEADDIM;
            kn = reinterpret_cast<const float4*>(key_cache   + o)[lane];
            vn = reinterpret_cast<const float4*>(value_cache + o)[lane];
        }
        float d = kc.x * q4.x + kc.y * q4.y + kc.z * q4.z + kc.w * q4.w;
        #pragma unroll
        for (int o2 = 16; o2; o2 >>= 1)
            d += __shfl_xor_sync(0xFFFFFFFFu, d, o2);
        d *= SCALE;

        const float mnew  = fmaxf(m, d);
        const float scale = __expf(m - mnew);   // first iter: exp(-inf - d) = 0
        const float pr    = __expf(d - mnew);
        s = s * scale + pr;
        acc.x = acc.x * scale + pr * vc.x;
        acc.y = acc.y * scale + pr * vc.y;
        acc.z = acc.z * scale + pr * vc.z;
        acc.w = acc.w * scale + pr * vc.w;
        m = mnew;
        kc = kn; vc = vn;
    }

    // ---- Merge 8 warp partials, emit split partial ----
    if (lane == 0) { s_wm[warp] = m; s_ws[warp] = s; }
    reinterpret_cast<float4*>(&s_acc[warp * HEADDIM])[lane] = acc;
    __syncthreads();

    if (tid < HEADDIM) {
        float gm = -INFINITY;
        #pragma unroll
        for (int w = 0; w < NWARPS; w++) gm = fmaxf(gm, s_wm[w]);
        float S = 0.0f, A = 0.0f;
        #pragma unroll
        for (int w = 0; w < NWARPS; w++) {
            const float wt = __expf(s_wm[w] - gm);   // idle warp: exp(-inf) = 0
            S += wt * s_ws[w];
            A += wt * s_acc[w * HEADDIM + tid];
        }
        g_acc[(size_t)p * HEADDIM + tid] = A;
        if (tid == 0) { g_m[p] = gm; g_s[p] = S; }
    }
}

__global__ __launch_bounds__(HEADDIM)
void paged_attn_reduce_kernel(float* __restrict__ out)
{
    const int bh = blockIdx.x;          // b*HEADS + h
    const int d  = threadIdx.x;

    float m[NSPLIT], s[NSPLIT];
    float gm = -INFINITY;
    #pragma unroll
    for (int i = 0; i < NSPLIT; i++) {
        m[i] = g_m[bh * NSPLIT + i];
        s[i] = g_s[bh * NSPLIT + i];
        gm = fmaxf(gm, m[i]);
    }
    float S = 0.0f, A = 0.0f;
    #pragma unroll
    for (int i = 0; i < NSPLIT; i++) {
        const float wt = __expf(m[i] - gm);
        S += wt * s[i];
        A += wt * g_acc[((size_t)bh * NSPLIT + i) * HEADDIM + d];
    }
    out[(size_t)bh * HEADDIM + d] = A / S;
}

extern "C" void kernel_launch(void* const* d_in, const int* in_sizes, int n_in,
                              void* d_out, int out_size)
{
    const float* query        = (const float*)d_in[0];
    const float* key_cache    = (const float*)d_in[1];
    const float* value_cache  = (const float*)d_in[2];
    const int*   block_tables = (const int*)d_in[3];
    const int*   context_lens = (const int*)d_in[4];
    float*       out          = (float*)d_out;

    dim3 grid(HEADS, BATCH, NSPLIT);
    paged_attn_split_kernel<<<grid, NTHREADS>>>(query, key_cache, value_cache,
                                                block_tables, context_lens);
    paged_attn_reduce_kernel<<<BATCH * HEADS, HEADDIM>>>(out);
}